// round 9
// baseline (speedup 1.0000x reference)
#include <cuda_runtime.h>
#include <cstdint>

#define BATCH 16
#define NPRED 22743
#define NCH   85
#define NCLS  80
#define TOPK  1000
#define TKPAD 1024
#define SCAP  12288
#define FULLMASK 0xFFFFFFFFu
#define NPRED_UP 23552
#define NROWS (BATCH * NPRED)

// ---------------- device scratch (no allocations allowed) ----------------
__device__ __align__(16) unsigned long long g_keys[NROWS]; // all rows (fallback)
__device__ __align__(16) unsigned long long g_cand[NROWS]; // per-image positives
__device__ float    g_conf[NROWS];
__device__ int      g_cls [NROWS];
__device__ unsigned g_cnt [BATCH];   // positives per image; nms resets to 0

// monotonic float -> uint mapping (larger float -> larger uint)
__device__ __forceinline__ unsigned ord32(float f) {
    unsigned u = __float_as_uint(f);
    return (u & 0x80000000u) ? ~u : (u | 0x80000000u);
}

// ---------------- kernel A: score / cls / key + positive compaction -------
#define RPB 32
#define TA  256
__global__ void score_kernel(const float* __restrict__ in) {
    __shared__ float srow[RPB * NCH];                 // 10880 B
    __shared__ unsigned long long s_key[RPB];
    __shared__ unsigned char s_pos[RPB];
    __shared__ unsigned char s_img[RPB];
    const int R0  = blockIdx.x * RPB;
    const int tid = threadIdx.x;
    int remRows = NROWS - R0; if (remRows > RPB) remRows = RPB;
    if (remRows == RPB) {
        const float4* src = (const float4*)(in + (size_t)R0 * NCH); // 32*85%4==0
        float4* dst = (float4*)srow;
        for (int idx = tid; idx < RPB * NCH / 4; idx += TA) dst[idx] = src[idx];
    } else {
        int remF = remRows * NCH;
        for (int i = tid; i < remF; i += TA) srow[i] = in[(size_t)R0 * NCH + i];
    }
    if (tid < RPB) { s_pos[tid] = 0; s_img[tid] = 0; }
    __syncthreads();

    const int warp = tid >> 5, lane = tid & 31;
    for (int rr = warp; rr < RPB; rr += TA / 32) {
        int gr = R0 + rr;
        if (gr >= NROWS) break;            // uniform within warp
        const float* row = srow + rr * NCH;
        float obj = row[4];
        unsigned u0 = __float_as_uint(row[5  + lane]);
        unsigned u1 = __float_as_uint(row[37 + lane]);
        unsigned u2 = (lane < 16) ? __float_as_uint(row[69 + lane]) : 0u;
        unsigned m  = __reduce_max_sync(FULLMASK, max(u0, max(u1, u2)));
        unsigned cd = (u0 == m) ? (unsigned)lane
                    : (u1 == m) ? (unsigned)(lane + 32)
                    : ((lane < 16) && (u2 == m)) ? (unsigned)(lane + 64) : 1024u;
        unsigned ci = __reduce_min_sync(FULLMASK, cd);
        if (lane == 0) {
            float conf  = __uint_as_float(m);
            float score = (obj >= 0.5f) ? __fmul_rn(obj, conf) : -1.0f;
            int b = gr / NPRED;
            unsigned n = (unsigned)(gr - b * NPRED);
            unsigned long long key =
                ((unsigned long long)ord32(score) << 32) | (unsigned)(~n);
            g_keys[gr] = key;
            g_conf[gr] = conf;
            g_cls [gr] = (int)ci;
            s_key[rr] = key;
            s_img[rr] = (unsigned char)b;
            s_pos[rr] = (score > 0.0f) ? 1 : 0;
        }
    }
    __syncthreads();

    // warp 0 aggregates: <=2 images per block (consecutive), 1 atomic each
    if (tid < 32) {
        bool pos = (s_pos[tid] != 0);
        int  img = (int)s_img[tid];
        int  b0  = __shfl_sync(FULLMASK, img, 0);
        bool in0 = pos && (img == b0);
        bool in1 = pos && (img != b0);      // img == b0+1 when set
        unsigned m0 = __ballot_sync(FULLMASK, in0);
        unsigned m1 = __ballot_sync(FULLMASK, in1);
        unsigned base = 0;
        if (tid == 0 && m0) base = atomicAdd(&g_cnt[b0],     (unsigned)__popc(m0));
        if (tid == 1 && m1) base = atomicAdd(&g_cnt[b0 + 1], (unsigned)__popc(m1));
        unsigned base0 = __shfl_sync(FULLMASK, base, 0);
        unsigned base1 = __shfl_sync(FULLMASK, base, 1);
        if (pos) {
            unsigned lm = (1u << tid) - 1u;
            unsigned idx = in0 ? (base0 + __popc(m0 & lm))
                               : (base1 + __popc(m1 & lm));
            g_cand[(size_t)img * NPRED + idx] = s_key[tid];
        }
    }
}

// ---------------- kernel B: per-image select + sort + per-class NMS -------
// SMEM (bytes): scand 98304 | sbox 16384 | skeys 8192 | whist 32768 |
//   sarea 4096 | sobj 4096 | sconf 4096 | scls 4096 | ccnt 512 | coff 512 |
//   clist 2048 | keepf 1024  = 176128
#define SMEM_B 176128

__global__ void __launch_bounds__(1024, 1)
nms_kernel(const float* __restrict__ in, float* __restrict__ out) {
    extern __shared__ unsigned char smem_raw[];
    unsigned long long* scand = (unsigned long long*)smem_raw;          // [12288]
    float4*             sbox  = (float4*)(scand + SCAP);                // [1024]
    unsigned long long* skeys = (unsigned long long*)(sbox + TKPAD);    // [1024]
    unsigned*           whist = (unsigned*)(skeys + TKPAD);             // [32][256]
    float*              sarea = (float*)(whist + 32 * 256);             // [1024]
    float*              sobj  = sarea + TKPAD;                          // [1024]
    float*              sconf = sobj + TKPAD;                           // [1024]
    int*                scls  = (int*)(sconf + TKPAD);                  // [1024]
    unsigned*           ccnt  = (unsigned*)(scls + TKPAD);              // [128]
    unsigned*           coff  = ccnt + 128;                             // [128]
    unsigned short*     clist = (unsigned short*)(coff + 128);          // [1024]
    unsigned char*      keepf = (unsigned char*)(clist + TKPAD);        // [1024]

    __shared__ int s_cnt2, s_r, s_done, s_fb, s_cp;
    __shared__ unsigned long long s_prefix;

    const int b    = blockIdx.x;
    const int tid  = threadIdx.x;
    const int lane = tid & 31;
    const int warp = tid >> 5;
    const unsigned long long* keys  = g_keys + (size_t)b * NPRED;
    const unsigned long long* candg = g_cand + (size_t)b * NPRED;

    if (tid == 0) {
        unsigned c = g_cnt[b];
        g_cnt[b] = 0;                        // reset for next graph replay
        s_cp  = (int)c;
        s_fb  = (c < TOPK) ? 1 : 0;          // rare: not enough positives
        s_cnt2 = 0;
    }
    if (tid < 128) ccnt[tid] = 0u;
    __syncthreads();

    if (!s_fb) {
        // ==== fast path: exact rank-1000 over the positive candidates ====
        const int cnt = s_cp;
        const bool useS = (cnt <= SCAP);
        const unsigned long long* cp = useS ? scand : candg;
        if (useS)
            for (int e = tid; e < cnt; e += 1024) scand[e] = candg[e];
        if (tid == 0) { s_prefix = 0ull; s_r = TOPK; s_done = 0; }
        const int iters = (cnt + 1023) >> 10;       // block-uniform
        unsigned long long mask = 0ull;
        for (int pass = 0; pass < 8; ++pass) {
            int shift = 56 - 8 * pass;
            for (int t = tid; t < 32 * 256; t += 1024) whist[t] = 0u;
            __syncthreads();
            unsigned long long pfx = s_prefix;
            unsigned* myh = whist + warp * 256;
            for (int it = 0; it < iters; ++it) {    // uniform trips
                int e = it * 1024 + tid;
                bool inb = e < cnt;
                unsigned long long k = inb ? cp[e] : 0ull;
                bool act = inb && ((k & mask) == pfx);
                unsigned d = (unsigned)((k >> shift) & 255ull);
                unsigned am = __ballot_sync(FULLMASK, act);
                if (act) {
                    unsigned peers = __match_any_sync(am, d);
                    if (lane == (int)(__ffs(peers) - 1)) myh[d] += __popc(peers);
                }
            }
            __syncthreads();
            if (tid < 256) {
                unsigned s = 0;
                #pragma unroll
                for (int w = 0; w < 32; ++w) s += whist[w * 256 + tid];
                whist[tid] = s;
            }
            __syncthreads();
            if (warp == 0) {                        // parallel digit scan
                int r = s_r;
                unsigned s8 = 0;
                #pragma unroll
                for (int i = 0; i < 8; ++i) s8 += whist[lane * 8 + i];
                unsigned i8 = s8;
                #pragma unroll
                for (int off = 1; off < 32; off <<= 1) {
                    unsigned o = __shfl_down_sync(FULLMASK, i8, off);
                    if (lane + off < 32) i8 += o;
                }
                unsigned sufE = i8 - s8;
                if ((int)sufE < r && (int)(sufE + s8) >= r) {
                    unsigned cum = sufE;
                    for (int d = 7; d >= 0; --d) {
                        unsigned c = whist[lane * 8 + d];
                        if ((int)(cum + c) >= r) {
                            s_prefix = s_prefix | ((unsigned long long)(lane * 8 + d) << shift);
                            s_r = r - (int)cum;
                            s_done = (c == (unsigned)(r - (int)cum));
                            break;
                        }
                        cum += c;
                    }
                }
            }
            mask |= (0xFFull << shift);
            __syncthreads();
            if (s_done) break;
        }
        const unsigned long long T = s_prefix;      // exactly TOPK keys >= T
        for (int it = 0; it < iters; ++it) {
            int e = it * 1024 + tid;
            if (e < cnt) {
                unsigned long long k = cp[e];
                if (k >= T) skeys[atomicAdd(&s_cnt2, 1)] = k;
            }
        }
    } else {
        // ==== fallback: full radix select over all global keys (exact) ====
        if (tid == 0) { s_prefix = 0ull; s_r = TOPK; s_done = 0; }
        unsigned long long mask = 0ull;
        for (int pass = 0; pass < 8; ++pass) {
            int shift = 56 - 8 * pass;
            for (int t = tid; t < 32 * 256; t += 1024) whist[t] = 0u;
            __syncthreads();
            unsigned long long pfx = s_prefix;
            unsigned* myh = whist + warp * 256;
            for (int e0 = 0; e0 < NPRED_UP; e0 += 1024) {
                int e = e0 + tid;
                bool inb = e < NPRED;
                unsigned long long k = inb ? keys[e] : 0ull;
                bool act = inb && ((k & mask) == pfx);
                unsigned d = (unsigned)((k >> shift) & 255ull);
                unsigned am = __ballot_sync(FULLMASK, act);
                if (act) {
                    unsigned peers = __match_any_sync(am, d);
                    if (lane == (int)(__ffs(peers) - 1)) myh[d] += __popc(peers);
                }
            }
            __syncthreads();
            if (tid < 256) {
                unsigned s = 0;
                #pragma unroll
                for (int w = 0; w < 32; ++w) s += whist[w * 256 + tid];
                whist[tid] = s;
            }
            __syncthreads();
            if (warp == 0) {
                int r = s_r;
                unsigned s8 = 0;
                #pragma unroll
                for (int i = 0; i < 8; ++i) s8 += whist[lane * 8 + i];
                unsigned i8 = s8;
                #pragma unroll
                for (int off = 1; off < 32; off <<= 1) {
                    unsigned o = __shfl_down_sync(FULLMASK, i8, off);
                    if (lane + off < 32) i8 += o;
                }
                unsigned sufE = i8 - s8;
                if ((int)sufE < r && (int)(sufE + s8) >= r) {
                    unsigned cum = sufE;
                    for (int d = 7; d >= 0; --d) {
                        unsigned c = whist[lane * 8 + d];
                        if ((int)(cum + c) >= r) {
                            s_prefix = s_prefix | ((unsigned long long)(lane * 8 + d) << shift);
                            s_r = r - (int)cum;
                            s_done = (c == (unsigned)(r - (int)cum));
                            break;
                        }
                        cum += c;
                    }
                }
            }
            mask |= (0xFFull << shift);
            __syncthreads();
            if (s_done) break;
        }
        const unsigned long long T = s_prefix;
        for (int e = tid; e < NPRED; e += 1024) {
            unsigned long long k = keys[e];
            if (k >= T) {
                int pos = atomicAdd(&s_cnt2, 1);
                if (pos < TKPAD) skeys[pos] = k;
            }
        }
    }
    __syncthreads();
    {
        int fc = s_cnt2;                             // == TOPK
        for (int t = tid; t < TKPAD; t += 1024)
            if (t >= fc) skeys[t] = 0ull;
    }
    __syncthreads();

    // ==== bitonic sort 1024 keys, descending ====
    for (int k = 2; k <= TKPAD; k <<= 1) {
        for (int j = k >> 1; j > 0; j >>= 1) {
            __syncthreads();
            int i = tid, ixj = tid ^ j;
            if (ixj > i) {
                unsigned long long a = skeys[i], c = skeys[ixj];
                bool descBlock = ((i & k) == 0);
                bool doSwap = descBlock ? (a < c) : (a > c);
                if (doSwap) { skeys[i] = c; skeys[ixj] = a; }
            }
        }
    }
    __syncthreads();

    // ==== gather det attributes + keep-init ====
    if (tid < TKPAD) {
        if (tid < TOPK) {
            unsigned long long key = skeys[tid];
            unsigned n = ~((unsigned)key);
            size_t r = (size_t)b * NPRED + n;
            const float* row = in + r * NCH;
            float cx = row[0], cy = row[1], w = row[2], h = row[3], obj = row[4];
            float hw = __fmul_rn(w, 0.5f), hh = __fmul_rn(h, 0.5f);
            float x1 = __fsub_rn(cx, hw), y1 = __fsub_rn(cy, hh);
            float x2 = __fadd_rn(cx, hw), y2 = __fadd_rn(cy, hh);
            sbox[tid]  = make_float4(x1, y1, x2, y2);
            sarea[tid] = __fmul_rn(fmaxf(__fsub_rn(x2, x1), 0.0f),
                                   fmaxf(__fsub_rn(y2, y1), 0.0f));
            sobj[tid]  = obj;
            sconf[tid] = g_conf[r];
            scls[tid]  = g_cls[r];
            keepf[tid] = ((unsigned)(key >> 32) > 0x80000000u) ? 1 : 0;
        } else {
            keepf[tid] = 0;
        }
    }
    __syncthreads();

    // ==== class bucketing (stable per-class ordered lists) ====
    for (int c = warp; c < NCLS; c += 32) {
        unsigned n = 0;
        for (int base = 0; base < TOPK; base += 32) {
            int j = base + lane;
            bool mt = (j < TOPK) && (scls[j] == c);
            n += __popc(__ballot_sync(FULLMASK, mt));
        }
        if (lane == 0) ccnt[c] = n;
    }
    __syncthreads();
    if (tid == 0) {
        unsigned acc = 0;
        for (int c = 0; c < NCLS; ++c) { coff[c] = acc; acc += ccnt[c]; }
    }
    __syncthreads();
    for (int c = warp; c < NCLS; c += 32) {
        unsigned off = coff[c];
        for (int base = 0; base < TOPK; base += 32) {
            int j = base + lane;
            bool mt = (j < TOPK) && (scls[j] == c);
            unsigned bm = __ballot_sync(FULLMASK, mt);
            if (mt) clist[off + __popc(bm & ((1u << lane) - 1u))] = (unsigned short)j;
            off += __popc(bm);
        }
    }
    __syncthreads();

    // ==== per-class greedy NMS, one warp per class ====
    for (int c = warp; c < NCLS; c += 32) {
        int n = (int)ccnt[c];
        int base = (int)coff[c];
        for (int i = 0; i < n; ++i) {
            __syncwarp();
            int pi = clist[base + i];
            if (!keepf[pi]) continue;
            float4 bi = sbox[pi];
            float  ai = sarea[pi];
            for (int jj = i + 1 + lane; jj < n; jj += 32) {
                int pj = clist[base + jj];
                float4 bj = sbox[pj];
                float xx1 = fmaxf(bi.x, bj.x), yy1 = fmaxf(bi.y, bj.y);
                float xx2 = fminf(bi.z, bj.z), yy2 = fminf(bi.w, bj.w);
                float iw  = fmaxf(__fsub_rn(xx2, xx1), 0.0f);
                float ih  = fmaxf(__fsub_rn(yy2, yy1), 0.0f);
                float inter = __fmul_rn(iw, ih);
                float uni   = __fsub_rn(__fadd_rn(ai, sarea[pj]), inter);
                float iou   = __fdiv_rn(inter, __fadd_rn(uni, 1e-16f));
                if (iou > 0.4f) keepf[pj] = 0;
            }
        }
    }
    __syncthreads();

    // ==== masked output (B, 1000, 7) ====
    if (tid < TOPK) {
        float m = keepf[tid] ? 1.0f : 0.0f;
        float4 bx = sbox[tid];
        float* o = out + ((size_t)b * TOPK + tid) * 7;
        o[0] = __fmul_rn(bx.x, m);
        o[1] = __fmul_rn(bx.y, m);
        o[2] = __fmul_rn(bx.z, m);
        o[3] = __fmul_rn(bx.w, m);
        o[4] = __fmul_rn(sobj[tid], m);
        o[5] = __fmul_rn(sconf[tid], m);
        o[6] = __fmul_rn((float)scls[tid], m);
    }
}

extern "C" void kernel_launch(void* const* d_in, const int* in_sizes, int n_in,
                              void* d_out, int out_size) {
    (void)in_sizes; (void)n_in; (void)out_size;
    const float* in  = (const float*)d_in[0];
    float*       out = (float*)d_out;

    score_kernel<<<(NROWS + RPB - 1) / RPB, TA>>>(in);
    cudaFuncSetAttribute(nms_kernel,
                         cudaFuncAttributeMaxDynamicSharedMemorySize, SMEM_B);
    nms_kernel<<<BATCH, 1024, SMEM_B>>>(in, out);
}

// round 10
// speedup vs baseline: 1.5157x; 1.5157x over previous
#include <cuda_runtime.h>
#include <cstdint>

#define BATCH 16
#define NPRED 22743
#define NCH   85
#define NCLS  80
#define TOPK  1000
#define SORTN 2048
#define CAND_CAP 2048
#define FULLMASK 0xFFFFFFFFu
#define NPRED_UP 23552
#define NROWS (BATCH * NPRED)
#define HBINS 16384            // key top-16 bits minus 0x8000, score>0 only

// ---------------- device scratch (no allocations allowed) ----------------
__device__ __align__(16) unsigned long long g_keys[NROWS];
__device__ float    g_conf[NROWS];          // valid for positive rows only
__device__ int      g_cls [NROWS];          // valid for positive rows only
__device__ __align__(16) unsigned g_hist[BATCH * HBINS]; // zero-init; nms re-zeroes

// key hi for score == -1.0f : ord32(-1.0f) = ~0xBF800000
#define NEG_HI 0x407FFFFFu

__device__ __forceinline__ unsigned ord32(float f) {
    unsigned u = __float_as_uint(f);
    return (u & 0x80000000u) ? ~u : (u | 0x80000000u);
}

// ---------------- kernel A: obj-gated score / cls / key / hist ------------
// Phase 1: thread-per-row obj prescan; negative rows finished immediately.
// Phase 2: warp-per-positive-row class argmax via REDUX.
#define TA 256
__global__ void score_kernel(const float* __restrict__ in) {
    __shared__ unsigned short s_list[TA];
    __shared__ float          s_obj [TA];
    __shared__ int s_np;
    const int R0  = blockIdx.x * TA;
    const int tid = threadIdx.x;
    const int lane = tid & 31, warp = tid >> 5;
    if (tid == 0) s_np = 0;
    __syncthreads();

    int gr = R0 + tid;
    bool inr = gr < NROWS;
    float obj = inr ? in[(size_t)gr * NCH + 4] : 0.0f;
    bool pos = inr && (obj >= 0.5f);
    if (inr && !pos) {                      // finish negative rows now
        int b = gr / NPRED;
        unsigned n = (unsigned)(gr - b * NPRED);
        g_keys[gr] = ((unsigned long long)NEG_HI << 32) | (unsigned)(~n);
    }
    // warp-aggregated append of positive rows
    unsigned bm = __ballot_sync(FULLMASK, pos);
    unsigned base = 0;
    if (lane == 0 && bm) base = atomicAdd(&s_np, __popc(bm));
    base = __shfl_sync(FULLMASK, base, 0);
    if (pos) {
        int slot = base + __popc(bm & ((1u << lane) - 1u));
        s_list[slot] = (unsigned short)tid;
    }
    s_obj[tid] = obj;
    __syncthreads();

    const int np = s_np;
    for (int i = warp; i < np; i += TA / 32) {
        int lt = (int)s_list[i];
        int r  = R0 + lt;
        const float* row = in + (size_t)r * NCH;
        unsigned u0 = __float_as_uint(row[5  + lane]);
        unsigned u1 = __float_as_uint(row[37 + lane]);
        unsigned u2 = (lane < 16) ? __float_as_uint(row[69 + lane]) : 0u;
        unsigned m  = __reduce_max_sync(FULLMASK, max(u0, max(u1, u2)));
        unsigned cd = (u0 == m) ? (unsigned)lane
                    : (u1 == m) ? (unsigned)(lane + 32)
                    : ((lane < 16) && (u2 == m)) ? (unsigned)(lane + 64) : 1024u;
        unsigned ci = __reduce_min_sync(FULLMASK, cd);
        if (lane == 0) {
            float conf  = __uint_as_float(m);
            float score = __fmul_rn(s_obj[lt], conf);   // obj >= 0.5 here
            int b = r / NPRED;
            unsigned n = (unsigned)(r - b * NPRED);
            unsigned long long key =
                ((unsigned long long)ord32(score) << 32) | (unsigned)(~n);
            g_keys[r] = key;
            g_conf[r] = conf;
            g_cls [r] = (int)ci;
            if (score > 0.0f)
                atomicAdd(&g_hist[b * HBINS + (int)((key >> 48) - 0x8000u)], 1u);
        }
    }
}

// ---------------- kernel B: per-image select + sort + per-class NMS -------
// SMEM: cand 16384 | sbox 16384 | whist 32768 | sarea 4096 | sobj 4096 |
//       sconf 4096 | scls 4096 | ccnt 512 | coff 512 | clist 2048 | keepf 1024
#define SMEM_B 86016

__global__ void __launch_bounds__(1024, 1)
nms_kernel(const float* __restrict__ in, float* __restrict__ out) {
    extern __shared__ unsigned char smem_raw[];
    unsigned long long* cand  = (unsigned long long*)smem_raw;          // [2048]
    float4*             sbox  = (float4*)(cand + SORTN);                // [1024]
    unsigned*           whist = (unsigned*)(sbox + 1024);               // [32][256]
    float*              sarea = (float*)(whist + 32 * 256);             // [1024]
    float*              sobj  = sarea + 1024;                           // [1024]
    float*              sconf = sobj + 1024;                            // [1024]
    int*                scls  = (int*)(sconf + 1024);                   // [1024]
    unsigned*           ccnt  = (unsigned*)(scls + 1024);               // [128]
    unsigned*           coff  = ccnt + 128;                             // [128]
    unsigned short*     clist = (unsigned short*)(coff + 128);          // [1024]
    unsigned char*      keepf = (unsigned char*)(clist + 1024);         // [1024]
    // Phase-1 aliases into whist (radix fallback runs later, no conflict)
    unsigned* csum  = whist;          // [256]
    unsigned* wtot  = whist + 256;    // [8]
    unsigned* wexcl = whist + 288;    // [32]

    __shared__ int s_found, s_chunk, s_bin, s_fb, s_cnt, s_r, s_done;
    __shared__ unsigned s_base, s_cntge;
    __shared__ unsigned long long s_prefix;

    const int b    = blockIdx.x;
    const int tid  = threadIdx.x;
    const int lane = tid & 31;
    const int warp = tid >> 5;
    const unsigned long long* keys = g_keys + (size_t)b * NPRED;
    unsigned* hb = g_hist + b * HBINS;

    if (tid == 0) { s_found = 0; s_fb = 0; s_cnt = 0; }
    if (tid < 128) ccnt[tid] = 0u;
    __syncthreads();

    // ==== Phase 1: 16-bit prefix of the 1000th-largest positive key ====
    unsigned vloc[4];                       // this thread's 4 chunk-contribs
    {
        const uint4* hb4 = (const uint4*)hb;
        #pragma unroll
        for (int i = 0; i < 4; ++i) {       // 16384 bins / (1024*4)
            uint4 h4 = hb4[i * 1024 + tid];
            unsigned s = h4.x + h4.y + h4.z + h4.w;
            vloc[i] = s;
            #pragma unroll
            for (int off = 1; off < 16; off <<= 1)
                s += __shfl_xor_sync(FULLMASK, s, off);
            if ((lane & 15) == 0)
                csum[i * 64 + (tid >> 4)] = s;   // 256 chunks of 64 bins
        }
    }
    __syncthreads();
    unsigned v = 0, incl = 0;
    if (warp < 8) {
        v = csum[tid];
        incl = v;
        #pragma unroll
        for (int off = 1; off < 32; off <<= 1) {
            unsigned o = __shfl_down_sync(FULLMASK, incl, off);
            if (lane + off < 32) incl += o;
        }
        if (lane == 0) wtot[warp] = incl;
    }
    __syncthreads();
    if (warp == 0) {
        unsigned t = (lane < 8) ? wtot[lane] : 0u;
        unsigned i2 = t;
        #pragma unroll
        for (int off = 1; off < 32; off <<= 1) {
            unsigned o = __shfl_down_sync(FULLMASK, i2, off);
            if (lane + off < 32) i2 += o;
        }
        wexcl[lane] = i2 - t;
    }
    __syncthreads();
    if (warp < 8) {
        unsigned sufE = wexcl[warp] + (incl - v);
        if (sufE < TOPK && sufE + v >= TOPK) {
            s_chunk = tid; s_base = sufE; s_found = 1;
        }
    }
    __syncthreads();
    if (s_found && warp == 0) {             // resolve 64 bins in chunk
        int c0 = s_chunk * 64;
        unsigned hlo = hb[c0 + 2 * lane];
        unsigned hhi = hb[c0 + 2 * lane + 1];
        unsigned p = hlo + hhi;
        unsigned ip = p;
        #pragma unroll
        for (int off = 1; off < 32; off <<= 1) {
            unsigned o = __shfl_down_sync(FULLMASK, ip, off);
            if (lane + off < 32) ip += o;
        }
        unsigned sufE = s_base + (ip - p);
        if (sufE < TOPK && sufE + p >= TOPK) {
            if (sufE + hhi >= TOPK) { s_bin = c0 + 2 * lane + 1; s_cntge = sufE + hhi; }
            else                    { s_bin = c0 + 2 * lane;     s_cntge = sufE + p;   }
        }
    }
    __syncthreads();
    // zero our hist slice for the next graph replay (reads are done)
    {
        uint4* hz = (uint4*)hb;
        #pragma unroll
        for (int i = 0; i < 4; ++i) hz[i * 1024 + tid] = make_uint4(0, 0, 0, 0);
    }
    if (tid == 0 && (!s_found || s_cntge > CAND_CAP)) s_fb = 1;
    __syncthreads();

    // ==== Phase 2: candidate compaction (fast path) ====
    if (!s_fb) {
        unsigned long long thr = (unsigned long long)(0x8000u + (unsigned)s_bin) << 48;
        for (int e = tid; e < NPRED; e += 1024) {
            unsigned long long k = keys[e];
            if (k >= thr) {
                int pos = atomicAdd(&s_cnt, 1);
                if (pos < CAND_CAP) cand[pos] = k;
            }
        }
        __syncthreads();
        if (tid == 0 && s_cnt > CAND_CAP) s_fb = 1;   // defensive
        __syncthreads();
    }

    // ==== Fallback: exact radix select over all global keys (rare) ====
    if (s_fb) {
        if (tid == 0) { s_prefix = 0ull; s_r = TOPK; s_done = 0; s_cnt = 0; }
        unsigned long long mask = 0ull;
        for (int pass = 0; pass < 8; ++pass) {
            int shift = 56 - 8 * pass;
            for (int t = tid; t < 32 * 256; t += 1024) whist[t] = 0u;
            __syncthreads();
            unsigned long long pfx = s_prefix;
            unsigned* myh = whist + warp * 256;
            for (int e0 = 0; e0 < NPRED_UP; e0 += 1024) {
                int e = e0 + tid;
                bool inb = e < NPRED;
                unsigned long long k = inb ? keys[e] : 0ull;
                bool act = inb && ((k & mask) == pfx);
                unsigned d = (unsigned)((k >> shift) & 255ull);
                unsigned am = __ballot_sync(FULLMASK, act);
                if (act) {
                    unsigned peers = __match_any_sync(am, d);
                    if (lane == (int)(__ffs(peers) - 1)) myh[d] += __popc(peers);
                }
            }
            __syncthreads();
            if (tid < 256) {
                unsigned s = 0;
                #pragma unroll
                for (int w = 0; w < 32; ++w) s += whist[w * 256 + tid];
                whist[tid] = s;
            }
            __syncthreads();
            if (warp == 0) {
                int r = s_r;
                unsigned s8 = 0;
                #pragma unroll
                for (int i = 0; i < 8; ++i) s8 += whist[lane * 8 + i];
                unsigned i8 = s8;
                #pragma unroll
                for (int off = 1; off < 32; off <<= 1) {
                    unsigned o = __shfl_down_sync(FULLMASK, i8, off);
                    if (lane + off < 32) i8 += o;
                }
                unsigned sufE = i8 - s8;
                if ((int)sufE < r && (int)(sufE + s8) >= r) {
                    unsigned cum = sufE;
                    for (int d = 7; d >= 0; --d) {
                        unsigned c = whist[lane * 8 + d];
                        if ((int)(cum + c) >= r) {
                            s_prefix = s_prefix | ((unsigned long long)(lane * 8 + d) << shift);
                            s_r = r - (int)cum;
                            s_done = (c == (unsigned)(r - (int)cum));
                            break;
                        }
                        cum += c;
                    }
                }
            }
            mask |= (0xFFull << shift);
            __syncthreads();
            if (s_done) break;
        }
        const unsigned long long T = s_prefix;        // exactly TOPK keys >= T
        for (int e = tid; e < NPRED; e += 1024) {
            unsigned long long k = keys[e];
            if (k >= T) {
                int pos = atomicAdd(&s_cnt, 1);
                if (pos < CAND_CAP) cand[pos] = k;
            }
        }
        __syncthreads();
    }

    // ==== Phase 3: pad + bitonic sort 2048 keys descending ====
    {
        int cnt = s_cnt; if (cnt > SORTN) cnt = SORTN;
        for (int t = tid; t < SORTN; t += 1024)
            if (t >= cnt) cand[t] = 0ull;
    }
    for (unsigned k = 2; k <= SORTN; k <<= 1) {
        for (unsigned j = k >> 1; j > 0; j >>= 1) {
            __syncthreads();
            unsigned i = tid;
            unsigned e = ((i & ~(j - 1u)) << 1) | (i & (j - 1u));
            unsigned p = e | j;
            unsigned long long a = cand[e], c2 = cand[p];
            bool desc = ((e & k) == 0);
            bool sw = desc ? (a < c2) : (a > c2);
            if (sw) { cand[e] = c2; cand[p] = a; }
        }
    }
    __syncthreads();

    // ==== Phase 4: gather det attributes + keep-init ====
    if (tid < 1024) {
        if (tid < TOPK) {
            unsigned long long key = cand[tid];
            unsigned n = ~((unsigned)key);
            size_t r = (size_t)b * NPRED + n;
            const float* row = in + r * NCH;
            float cx = row[0], cy = row[1], w = row[2], h = row[3], obj = row[4];
            float hw = __fmul_rn(w, 0.5f), hh = __fmul_rn(h, 0.5f);
            float x1 = __fsub_rn(cx, hw), y1 = __fsub_rn(cy, hh);
            float x2 = __fadd_rn(cx, hw), y2 = __fadd_rn(cy, hh);
            sbox[tid]  = make_float4(x1, y1, x2, y2);
            sarea[tid] = __fmul_rn(fmaxf(__fsub_rn(x2, x1), 0.0f),
                                   fmaxf(__fsub_rn(y2, y1), 0.0f));
            sobj[tid]  = obj;
            bool posk = ((unsigned)(key >> 32) > 0x80000000u);
            keepf[tid] = posk ? 1 : 0;
            if (!s_fb) {                    // positives: stored conf/cls valid
                sconf[tid] = g_conf[r];
                scls[tid]  = g_cls[r];
            }
        } else {
            keepf[tid] = 0;
            if (s_fb) { /* nothing */ }
        }
    }
    if (s_fb) {                             // recompute conf/cls (exact, rare)
        __syncthreads();
        for (int i = warp; i < TOPK; i += 32) {
            unsigned long long key = cand[i];
            unsigned n = ~((unsigned)key);
            const float* row = in + ((size_t)b * NPRED + n) * NCH;
            unsigned u0 = __float_as_uint(row[5  + lane]);
            unsigned u1 = __float_as_uint(row[37 + lane]);
            unsigned u2 = (lane < 16) ? __float_as_uint(row[69 + lane]) : 0u;
            unsigned m  = __reduce_max_sync(FULLMASK, max(u0, max(u1, u2)));
            unsigned cd = (u0 == m) ? (unsigned)lane
                        : (u1 == m) ? (unsigned)(lane + 32)
                        : ((lane < 16) && (u2 == m)) ? (unsigned)(lane + 64) : 1024u;
            unsigned ci = __reduce_min_sync(FULLMASK, cd);
            if (lane == 0) { sconf[i] = __uint_as_float(m); scls[i] = (int)ci; }
        }
    }
    __syncthreads();

    // ==== Phase 5: class bucketing (stable per-class ordered lists) ====
    for (int c = warp; c < NCLS; c += 32) {
        unsigned n = 0;
        for (int base = 0; base < TOPK; base += 32) {
            int j = base + lane;
            bool mt = (j < TOPK) && (scls[j] == c);
            n += __popc(__ballot_sync(FULLMASK, mt));
        }
        if (lane == 0) ccnt[c] = n;
    }
    __syncthreads();
    if (tid == 0) {
        unsigned acc = 0;
        for (int c = 0; c < NCLS; ++c) { coff[c] = acc; acc += ccnt[c]; }
    }
    __syncthreads();
    for (int c = warp; c < NCLS; c += 32) {
        unsigned off = coff[c];
        for (int base = 0; base < TOPK; base += 32) {
            int j = base + lane;
            bool mt = (j < TOPK) && (scls[j] == c);
            unsigned bm = __ballot_sync(FULLMASK, mt);
            if (mt) clist[off + __popc(bm & ((1u << lane) - 1u))] = (unsigned short)j;
            off += __popc(bm);
        }
    }
    __syncthreads();

    // ==== Phase 6: per-class greedy NMS, one warp per class ====
    for (int c = warp; c < NCLS; c += 32) {
        int n = (int)ccnt[c];
        int base = (int)coff[c];
        for (int i = 0; i < n; ++i) {
            __syncwarp();
            int pi = clist[base + i];
            if (!keepf[pi]) continue;
            float4 bi = sbox[pi];
            float  ai = sarea[pi];
            for (int jj = i + 1 + lane; jj < n; jj += 32) {
                int pj = clist[base + jj];
                float4 bj = sbox[pj];
                float xx1 = fmaxf(bi.x, bj.x), yy1 = fmaxf(bi.y, bj.y);
                float xx2 = fminf(bi.z, bj.z), yy2 = fminf(bi.w, bj.w);
                float iw  = fmaxf(__fsub_rn(xx2, xx1), 0.0f);
                float ih  = fmaxf(__fsub_rn(yy2, yy1), 0.0f);
                float inter = __fmul_rn(iw, ih);
                float uni   = __fsub_rn(__fadd_rn(ai, sarea[pj]), inter);
                float iou   = __fdiv_rn(inter, __fadd_rn(uni, 1e-16f));
                if (iou > 0.4f) keepf[pj] = 0;
            }
        }
    }
    __syncthreads();

    // ==== Phase 7: masked output (B, 1000, 7) ====
    if (tid < TOPK) {
        float m = keepf[tid] ? 1.0f : 0.0f;
        float4 bx = sbox[tid];
        float* o = out + ((size_t)b * TOPK + tid) * 7;
        o[0] = __fmul_rn(bx.x, m);
        o[1] = __fmul_rn(bx.y, m);
        o[2] = __fmul_rn(bx.z, m);
        o[3] = __fmul_rn(bx.w, m);
        o[4] = __fmul_rn(sobj[tid], m);
        o[5] = __fmul_rn(sconf[tid], m);
        o[6] = __fmul_rn((float)scls[tid], m);
    }
}

extern "C" void kernel_launch(void* const* d_in, const int* in_sizes, int n_in,
                              void* d_out, int out_size) {
    (void)in_sizes; (void)n_in; (void)out_size;
    const float* in  = (const float*)d_in[0];
    float*       out = (float*)d_out;

    score_kernel<<<(NROWS + TA - 1) / TA, TA>>>(in);
    cudaFuncSetAttribute(nms_kernel,
                         cudaFuncAttributeMaxDynamicSharedMemorySize, SMEM_B);
    nms_kernel<<<BATCH, 1024, SMEM_B>>>(in, out);
}